// round 5
// baseline (speedup 1.0000x reference)
#include <cuda_runtime.h>
#include <math.h>

// Shapes (fixed by setup_inputs): B=4, N=64, T=64, FH=128, FO=64
#define N_  64
#define T_  64
#define FH_ 128
#define FO_ 64

// Scratch (device globals; no allocation allowed)
__device__ float g_wh[4 * N_ * T_ * FO_];   // Wh[b][n][t][o]
__device__ float g_pr[4 * N_ * T_];         // pr[b][t][n]  (t-major for main kernel)
__device__ float g_ps[4 * N_ * T_];
__device__ float g_wr[FH_];
__device__ float g_ws[FH_];
__device__ float g_cr;
__device__ float g_cs;
__device__ float g_cnt[N_ * N_];

// ---------------------------------------------------------------------------
// Kernel 1: prep — fold a_w into W_fc / b_fc ; zero cnt
// ---------------------------------------------------------------------------
__global__ void prep_kernel(const float* __restrict__ W,   // [FO][FH]
                            const float* __restrict__ bfc, // [FO]
                            const float* __restrict__ aw)  // [2*FO]
{
    int k = threadIdx.x; // 0..127
    float wr = 0.f, ws = 0.f;
    #pragma unroll 8
    for (int o = 0; o < FO_; o++) {
        float w = W[o * FH_ + k];
        wr += aw[o] * w;
        ws += aw[FO_ + o] * w;
    }
    g_wr[k] = wr;
    g_ws[k] = ws;
    if (k == 0) {
        float c = 0.f;
        for (int o = 0; o < FO_; o++) c += aw[o] * bfc[o];
        g_cr = c;
    }
    if (k == 1) {
        float c = 0.f;
        for (int o = 0; o < FO_; o++) c += aw[FO_ + o] * bfc[o];
        g_cs = c;
    }
    // zero cnt (4096 entries / 128 threads = 32 each)
    for (int i = 0; i < 32; i++) g_cnt[k + i * 128] = 0.f;
}

// ---------------------------------------------------------------------------
// Kernel 2: edge multiplicity via argmax (matches jnp.argmax first-max rule)
// ---------------------------------------------------------------------------
__global__ void edge_kernel(const float* __restrict__ rr,
                            const float* __restrict__ rs, int E)
{
    int e = blockIdx.x * blockDim.x + threadIdx.x;
    if (e >= E) return;
    const float* r = rr + (size_t)e * N_;
    const float* s = rs + (size_t)e * N_;
    float mr = r[0], ms = s[0];
    int ir = 0, is = 0;
    #pragma unroll 8
    for (int j = 1; j < N_; j++) {
        float vr = r[j], vs = s[j];
        if (vr > mr) { mr = vr; ir = j; }
        if (vs > ms) { ms = vs; is = j; }
    }
    atomicAdd(&g_cnt[ir * N_ + is], 1.0f);
}

// ---------------------------------------------------------------------------
// Kernel 3: Wh = h @ W^T + b, plus pr/ps projections.
// One block per (b,n). 256 threads. 4x-t x 16-o register tile per thread.
// dyn smem: sh_h[64][129] + sh_Wt[128][68]
// ---------------------------------------------------------------------------
#define SHH_STRIDE 129
#define SWT_STRIDE 68

__global__ void __launch_bounds__(256, 2)
wh_kernel(const float* __restrict__ h,    // [B][N][T][FH]
          const float* __restrict__ W,    // [FO][FH]
          const float* __restrict__ bfc)  // [FO]
{
    extern __shared__ float smem[];
    float* sh_h  = smem;                       // 64*129
    float* sh_Wt = smem + N_ * SHH_STRIDE;     // 128*68  (k-major, padded)

    const int n = blockIdx.x;
    const int b = blockIdx.y;
    const int tid = threadIdx.x;

    const float* hb = h + ((size_t)(b * N_ + n)) * T_ * FH_;

    // stage h tile (t-major) and W transposed (k-major)
    for (int i = 0; i < T_ * FH_ / 256; i++) {
        int idx = tid + i * 256;
        int t = idx >> 7, k = idx & 127;
        sh_h[t * SHH_STRIDE + k] = hb[idx];
    }
    for (int i = 0; i < FO_ * FH_ / 256; i++) {
        int idx = tid + i * 256;
        int o = idx >> 7, k = idx & 127;
        sh_Wt[k * SWT_STRIDE + o] = W[idx];
    }
    __syncthreads();

    // main GEMM: thread (t = tid>>2, og = tid&3) computes o = og*4 + c*16 + j
    const int t  = tid >> 2;
    const int og = tid & 3;

    float acc[16];
    #pragma unroll
    for (int c = 0; c < 4; c++)
        #pragma unroll
        for (int j = 0; j < 4; j++)
            acc[c * 4 + j] = bfc[og * 4 + c * 16 + j];

    const float* hrow = sh_h + t * SHH_STRIDE;
    #pragma unroll 4
    for (int k = 0; k < FH_; k++) {
        float hv = hrow[k];
        const float* wk = sh_Wt + k * SWT_STRIDE + og * 4;
        #pragma unroll
        for (int c = 0; c < 4; c++) {
            float4 w = *reinterpret_cast<const float4*>(wk + c * 16);
            acc[c * 4 + 0] = fmaf(hv, w.x, acc[c * 4 + 0]);
            acc[c * 4 + 1] = fmaf(hv, w.y, acc[c * 4 + 1]);
            acc[c * 4 + 2] = fmaf(hv, w.z, acc[c * 4 + 2]);
            acc[c * 4 + 3] = fmaf(hv, w.w, acc[c * 4 + 3]);
        }
    }

    float* out = g_wh + (((size_t)(b * N_ + n)) * T_ + t) * FO_;
    #pragma unroll
    for (int c = 0; c < 4; c++) {
        float4 v = make_float4(acc[c * 4 + 0], acc[c * 4 + 1],
                               acc[c * 4 + 2], acc[c * 4 + 3]);
        *reinterpret_cast<float4*>(out + og * 4 + c * 16) = v;
    }

    // pr / ps projections (threads 0..127)
    if (tid < 128) {
        int tt = tid & 63;
        const float* hr = sh_h + tt * SHH_STRIDE;
        if (tid < 64) {
            float a = g_cr;
            #pragma unroll 8
            for (int k = 0; k < FH_; k++) a = fmaf(hr[k], g_wr[k], a);
            g_pr[b * (T_ * N_) + tt * N_ + n] = a;
        } else {
            float a = g_cs;
            #pragma unroll 8
            for (int k = 0; k < FH_; k++) a = fmaf(hr[k], g_ws[k], a);
            g_ps[b * (T_ * N_) + tt * N_ + n] = a;
        }
    }
}

// ---------------------------------------------------------------------------
// Kernel 4: fused edge scores -> A / A_sym / A_norm / h_p. Block per (b,t).
// ---------------------------------------------------------------------------
#define SA_STRIDE 65

__global__ void __launch_bounds__(256, 4)
main_kernel(const float* __restrict__ ab_ptr,
            float* __restrict__ out, int B)
{
    __shared__ float sA[N_ * SA_STRIDE];   // 16640 B
    __shared__ float sWh[N_ * FO_];        // 16384 B
    __shared__ float sPr[N_];
    __shared__ float sPs[N_];
    __shared__ float sRow[N_];

    const int t = blockIdx.x;
    const int b = blockIdx.y;
    const int tid = threadIdx.x;
    const float ab = ab_ptr[0];

    if (tid < N_)            sPr[tid]       = g_pr[b * (T_ * N_) + t * N_ + tid];
    else if (tid < 2 * N_)   sPs[tid - N_]  = g_ps[b * (T_ * N_) + t * N_ + (tid - N_)];
    __syncthreads();

    // fill sA (edge scores) and stage Wh[:,t,:] tile
    const float* whb = g_wh + (size_t)b * N_ * T_ * FO_ + (size_t)t * FO_;
    #pragma unroll
    for (int i = 0; i < 16; i++) {
        int idx = tid + i * 256;
        int r = idx >> 6, s = idx & 63;
        float c = g_cnt[idx];
        float v = 0.f;
        if (c != 0.f) {
            float x = sPr[r] + sPs[s] + ab;
            x = (x > 0.f) ? x : 0.2f * x;
            v = c * expf(x);
        }
        sA[r * SA_STRIDE + s] = v;
        sWh[idx] = whb[(size_t)r * (T_ * FO_) + s];   // m=r, o=s
    }
    __syncthreads();

    // row sums
    if (tid < N_) {
        float sum = 0.f;
        const float* row = sA + tid * SA_STRIDE;
        #pragma unroll 8
        for (int s = 0; s < N_; s++) sum += row[s];
        sRow[tid] = sum;
    }
    __syncthreads();

    const size_t npp = (size_t)B * T_ * N_ * N_;   // elements per (B,T,N,N) tensor
    float* hp_out    = out;
    float* A_out     = out + (size_t)B * N_ * T_ * FO_;
    float* Asym_out  = A_out + npp;
    float* Anorm_out = Asym_out + npp;
    const size_t abase = ((size_t)(b * T_ + t)) * (N_ * N_);

    // write A and A_sym (needs transposed reads — before in-place normalize)
    #pragma unroll
    for (int i = 0; i < 16; i++) {
        int idx = tid + i * 256;
        int r = idx >> 6, s = idx & 63;
        float v = sA[r * SA_STRIDE + s];
        A_out[abase + idx]    = v;
        Asym_out[abase + idx] = 0.5f * (v + sA[s * SA_STRIDE + r]);
    }
    __syncthreads();

    // normalize in place and write A_norm
    #pragma unroll
    for (int i = 0; i < 16; i++) {
        int idx = tid + i * 256;
        int r = idx >> 6, s = idx & 63;
        float v = sA[r * SA_STRIDE + s] / sRow[r];
        Anorm_out[abase + idx] = v;
        sA[r * SA_STRIDE + s] = v;
    }
    __syncthreads();

    // h_p[b,n,t,o] = relu( sum_m A_norm[n,m] * Wh[m,o] )
    const int n  = tid >> 2;
    const int og = tid & 3;
    float acc[16];
    #pragma unroll
    for (int i = 0; i < 16; i++) acc[i] = 0.f;

    const float* arow = sA + n * SA_STRIDE;
    #pragma unroll 4
    for (int m = 0; m < N_; m++) {
        float a = arow[m];
        const float* wm = sWh + m * FO_ + og * 4;
        #pragma unroll
        for (int c = 0; c < 4; c++) {
            float4 w = *reinterpret_cast<const float4*>(wm + c * 16);
            acc[c * 4 + 0] = fmaf(a, w.x, acc[c * 4 + 0]);
            acc[c * 4 + 1] = fmaf(a, w.y, acc[c * 4 + 1]);
            acc[c * 4 + 2] = fmaf(a, w.z, acc[c * 4 + 2]);
            acc[c * 4 + 3] = fmaf(a, w.w, acc[c * 4 + 3]);
        }
    }

    float* hp = hp_out + (size_t)b * (N_ * T_ * FO_) + (size_t)n * (T_ * FO_) + (size_t)t * FO_;
    #pragma unroll
    for (int c = 0; c < 4; c++) {
        float4 v = make_float4(fmaxf(acc[c * 4 + 0], 0.f), fmaxf(acc[c * 4 + 1], 0.f),
                               fmaxf(acc[c * 4 + 2], 0.f), fmaxf(acc[c * 4 + 3], 0.f));
        *reinterpret_cast<float4*>(hp + og * 4 + c * 16) = v;
    }
}

// ---------------------------------------------------------------------------
extern "C" void kernel_launch(void* const* d_in, const int* in_sizes, int n_in,
                              void* d_out, int out_size)
{
    const float* h   = (const float*)d_in[0];
    const float* rr  = (const float*)d_in[1];
    const float* rs  = (const float*)d_in[2];
    const float* Wfc = (const float*)d_in[3];
    const float* bfc = (const float*)d_in[4];
    const float* aw  = (const float*)d_in[5];
    const float* abp = (const float*)d_in[6];

    const int B = in_sizes[0] / (N_ * T_ * FH_);
    const int E = in_sizes[1] / N_;

    static bool attr_done = false;
    const int wh_smem = (N_ * SHH_STRIDE + FH_ * SWT_STRIDE) * sizeof(float);
    if (!attr_done) {
        cudaFuncSetAttribute(wh_kernel, cudaFuncAttributeMaxDynamicSharedMemorySize, wh_smem);
        attr_done = true;
    }

    prep_kernel<<<1, 128>>>(Wfc, bfc, aw);
    edge_kernel<<<(E + 127) / 128, 128>>>(rr, rs, E);
    wh_kernel<<<dim3(N_, B), 256, wh_smem>>>(h, Wfc, bfc);
    main_kernel<<<dim3(T_, B), 256>>>(abp, (float*)d_out, B);
}